// round 15
// baseline (speedup 1.0000x reference)
#include <cuda_runtime.h>
#include <cuda_bf16.h>
#include <cuda_fp16.h>
#include <cstdint>

// Problem constants
#define Bb 4
#define Lq 2052
#define Cc 1024
#define Hh 16
#define Dd 64
#define NREG 4
#define ROWS (Bb * Lq)                  // 8208
#define ROPE_PLANE ((Lq - NREG) * Dd)   // 2048*64
#define LPAD 2064                       // padded L for transposed V rows

// -------- scratch (device globals; no allocation allowed) ------------------
__device__ float g_qkv[(size_t)ROWS * 3 * Cc];       // QKV GEMM output
__device__ float g_q[(size_t)Bb * Hh * Lq * Dd];     // Q fp32 [B,H,L,D]
__device__ __nv_bfloat16 g_khi[(size_t)Bb * Hh * Lq * Dd];
__device__ __nv_bfloat16 g_klo[(size_t)Bb * Hh * Lq * Dd];
__device__ __half g_vt[(size_t)Bb * Hh * Dd * LPAD];  // V^T fp16 [B,H,D,Lpad]
__device__ float g_attn[(size_t)ROWS * Cc];          // attention out [B,L,C]
__device__ float g_ln[(size_t)ROWS * Cc];            // LN out (tf32-rounded)
__device__ float g_xr[(size_t)ROWS * Cc];            // x rounded to tf32
__device__ float g_wqkvT[(size_t)3 * Cc * Cc];       // Wqkv^T [3C][C] tf32
__device__ float g_wprojT[(size_t)Cc * Cc];          // Wproj^T [C][C] tf32

// ---------------------------------------------------------------------------
// helpers
// ---------------------------------------------------------------------------
__device__ __forceinline__ unsigned f2tf32(float f) {
    unsigned u;
    asm("cvt.rna.tf32.f32 %0, %1;" : "=r"(u) : "f"(f));
    return u;
}

__device__ __forceinline__ float ex2f(float x) {
    float r;
    asm("ex2.approx.ftz.f32 %0, %1;" : "=f"(r) : "f"(x));
    return r;
}

__device__ __forceinline__ void mma_tf32(float* c, const unsigned* a,
                                         const unsigned* b) {
    asm volatile(
        "mma.sync.aligned.m16n8k8.row.col.f32.tf32.tf32.f32 "
        "{%0,%1,%2,%3}, {%4,%5,%6,%7}, {%8,%9}, {%0,%1,%2,%3};"
        : "+f"(c[0]), "+f"(c[1]), "+f"(c[2]), "+f"(c[3])
        : "r"(a[0]), "r"(a[1]), "r"(a[2]), "r"(a[3]), "r"(b[0]), "r"(b[1]));
}

__device__ __forceinline__ void mma_bf16(float* c, const unsigned* a,
                                         const unsigned* b) {
    asm volatile(
        "mma.sync.aligned.m16n8k16.row.col.f32.bf16.bf16.f32 "
        "{%0,%1,%2,%3}, {%4,%5,%6,%7}, {%8,%9}, {%0,%1,%2,%3};"
        : "+f"(c[0]), "+f"(c[1]), "+f"(c[2]), "+f"(c[3])
        : "r"(a[0]), "r"(a[1]), "r"(a[2]), "r"(a[3]), "r"(b[0]), "r"(b[1]));
}

__device__ __forceinline__ void mma_f16(float* c, const unsigned* a,
                                        const unsigned* b) {
    asm volatile(
        "mma.sync.aligned.m16n8k16.row.col.f32.f16.f16.f32 "
        "{%0,%1,%2,%3}, {%4,%5,%6,%7}, {%8,%9}, {%0,%1,%2,%3};"
        : "+f"(c[0]), "+f"(c[1]), "+f"(c[2]), "+f"(c[3])
        : "r"(a[0]), "r"(a[1]), "r"(a[2]), "r"(a[3]), "r"(b[0]), "r"(b[1]));
}

__device__ __forceinline__ void ldsm_x4(unsigned& r0, unsigned& r1,
                                        unsigned& r2, unsigned& r3,
                                        unsigned addr) {
    asm volatile(
        "ldmatrix.sync.aligned.m8n8.x4.shared.b16 {%0,%1,%2,%3}, [%4];"
        : "=r"(r0), "=r"(r1), "=r"(r2), "=r"(r3)
        : "r"(addr));
}

__device__ __forceinline__ unsigned pack_bf16(float x, float y) {
    __nv_bfloat162 t = __floats2bfloat162_rn(x, y);
    return *(unsigned*)&t;
}

__device__ __forceinline__ void split2(float x, float y, unsigned& hi,
                                       unsigned& lo) {
    __nv_bfloat16 hx = __float2bfloat16_rn(x);
    __nv_bfloat16 hy = __float2bfloat16_rn(y);
    float rx = x - __bfloat162float(hx);
    float ry = y - __bfloat162float(hy);
    __nv_bfloat162 h;
    h.x = hx;
    h.y = hy;
    hi = *(unsigned*)&h;
    lo = pack_bf16(rx, ry);
}

__device__ __forceinline__ unsigned pack_h2(float x, float y) {
    __half2 t = __floats2half2_rn(x, y);
    return *(unsigned*)&t;
}

__device__ __forceinline__ unsigned smaddr(const void* p) {
    return (unsigned)__cvta_generic_to_shared(p);
}
__device__ __forceinline__ void cpa16(unsigned dst, const void* src, int sz) {
    asm volatile("cp.async.cg.shared.global [%0], [%1], 16, %2;" ::"r"(dst),
                 "l"(src), "r"(sz));
}
#define CPA_COMMIT asm volatile("cp.async.commit_group;")
#define CPA_WAIT0 asm volatile("cp.async.wait_group 0;" ::: "memory")

// ---------------------------------------------------------------------------
// prep: round x to tf32; transpose+round W -> WT [N][K]
// ---------------------------------------------------------------------------
__global__ void round_tf32_kernel(const float* __restrict__ src,
                                  float* __restrict__ dst, int n4) {
    int i = blockIdx.x * blockDim.x + threadIdx.x;
    if (i >= n4) return;
    float4 v = ((const float4*)src)[i];
    v.x = __uint_as_float(f2tf32(v.x));
    v.y = __uint_as_float(f2tf32(v.y));
    v.z = __uint_as_float(f2tf32(v.z));
    v.w = __uint_as_float(f2tf32(v.w));
    ((float4*)dst)[i] = v;
}

__global__ void transpose_round_kernel(const float* __restrict__ W,
                                       float* __restrict__ WT, int K, int N) {
    __shared__ float tile[32][33];
    int k0 = blockIdx.y * 32, n0 = blockIdx.x * 32;
    int tx = threadIdx.x, ty = threadIdx.y;
#pragma unroll
    for (int j = 0; j < 4; j++)
        tile[ty + j * 8][tx] = W[(size_t)(k0 + ty + j * 8) * N + n0 + tx];
    __syncthreads();
#pragma unroll
    for (int j = 0; j < 4; j++)
        WT[(size_t)(n0 + ty + j * 8) * K + k0 + tx] =
            __uint_as_float(f2tf32(tile[tx][ty + j * 8]));
}

// ---------------------------------------------------------------------------
// tf32 GEMM: block 128x256, BK=64, warp 64x64, double-buffered cp.async,
// both operands k-major + ldmatrix.  (round-11 passing version, unchanged)
// ---------------------------------------------------------------------------
#define GEMM_SMEM ((2 * 128 * 68 + 2 * 256 * 68) * 4)

__global__ __launch_bounds__(256) void gemm_tf32_db(
    const float* __restrict__ A, const float* __restrict__ BT,
    const float* __restrict__ bias, float* __restrict__ Cm,
    int M, int N, int K) {
    extern __shared__ float gsm[];
    float(*As)[128][68] = (float(*)[128][68])gsm;
    float(*Bs)[256][68] = (float(*)[256][68])(gsm + 2 * 128 * 68);

    int tid = threadIdx.x;
    int warp = tid >> 5, lane = tid & 31;
    int g = lane >> 2, t = lane & 3;
    int wm = (warp >> 2) * 64, wn = (warp & 3) * 64;
    int m0 = blockIdx.y * 128, n0 = blockIdx.x * 256;

    int j = lane >> 3, r = lane & 7;
    int aoff = ((j & 1) * 8 + r) * 68 + (j >> 1) * 4;
    int boff = ((j >> 1) * 8 + r) * 68 + (j & 1) * 4;

    float acc[4][8][4];
#pragma unroll
    for (int mt = 0; mt < 4; mt++)
#pragma unroll
        for (int nt = 0; nt < 8; nt++)
#pragma unroll
            for (int q = 0; q < 4; q++) acc[mt][nt][q] = 0.f;

    auto stage = [&](int buf, int k0) {
#pragma unroll
        for (int p = 0; p < 8; p++) {
            int it = tid + p * 256;
            int row = it >> 4, c4 = (it & 15) * 4;
            int ar = m0 + row;
            int arc = ar < M ? ar : 0;
            cpa16(smaddr(&As[buf][row][c4]),
                  &A[(size_t)arc * K + k0 + c4], ar < M ? 16 : 0);
        }
#pragma unroll
        for (int p = 0; p < 16; p++) {
            int it = tid + p * 256;
            int row = it >> 4, c4 = (it & 15) * 4;
            cpa16(smaddr(&Bs[buf][row][c4]),
                  &BT[(size_t)(n0 + row) * K + k0 + c4], 16);
        }
    };

    int nk = K / 64;  // 16
    stage(0, 0);
    CPA_COMMIT;

    for (int kt = 0; kt < nk; kt++) {
        CPA_WAIT0;
        __syncthreads();
        if (kt + 1 < nk) {
            stage((kt + 1) & 1, (kt + 1) * 64);
            CPA_COMMIT;
        }
        int buf = kt & 1;
        unsigned Abase = smaddr(&As[buf][0][0]);
        unsigned Bbase = smaddr(&Bs[buf][0][0]);
#pragma unroll
        for (int ks = 0; ks < 8; ks++) {
            unsigned af[4][4], bf[8][2];
#pragma unroll
            for (int mt = 0; mt < 4; mt++) {
                unsigned ad =
                    Abase + ((wm + mt * 16) * 68 + ks * 8 + aoff) * 4;
                ldsm_x4(af[mt][0], af[mt][1], af[mt][2], af[mt][3], ad);
            }
#pragma unroll
            for (int pr = 0; pr < 4; pr++) {
                unsigned bd =
                    Bbase + ((wn + pr * 16) * 68 + ks * 8 + boff) * 4;
                ldsm_x4(bf[2 * pr][0], bf[2 * pr][1], bf[2 * pr + 1][0],
                        bf[2 * pr + 1][1], bd);
            }
#pragma unroll
            for (int mt = 0; mt < 4; mt++)
#pragma unroll
                for (int nt = 0; nt < 8; nt++)
                    mma_tf32(acc[mt][nt], af[mt], bf[nt]);
        }
    }

#pragma unroll
    for (int mt = 0; mt < 4; mt++) {
        int row = m0 + wm + mt * 16 + g;
#pragma unroll
        for (int nt = 0; nt < 8; nt++) {
            int col = n0 + wn + nt * 8 + t * 2;
            float b0 = bias[col], b1 = bias[col + 1];
            if (row < M) {
                *(float2*)&Cm[(size_t)row * N + col] =
                    make_float2(acc[mt][nt][0] + b0, acc[mt][nt][1] + b1);
            }
            if (row + 8 < M) {
                *(float2*)&Cm[(size_t)(row + 8) * N + col] =
                    make_float2(acc[mt][nt][2] + b0, acc[mt][nt][3] + b1);
            }
        }
    }
}

// ---------------------------------------------------------------------------
// RoPE + split + transpose: Q fp32; K hi/lo bf16 [B,H,L,D]; V^T fp16 [B,H,D,LPAD]
// ---------------------------------------------------------------------------
__global__ __launch_bounds__(256) void rope_split_kernel(
    const float* __restrict__ qkv, const float* __restrict__ rope,
    float* __restrict__ Q, __nv_bfloat16* __restrict__ KHI,
    __nv_bfloat16* __restrict__ KLO, __half* __restrict__ VT) {
    __shared__ __half vh[64][72];  // [d][l_local]
    int lt0 = blockIdx.x * 64, h = blockIdx.y, b = blockIdx.z;
    int tid = threadIdx.x;
    size_t bh = (size_t)(b * Hh + h);

    for (int it = tid; it < 64 * 16; it += 256) {
        int ll = it >> 4, d4 = (it & 15) * 4;
        int l = lt0 + ll;
        if (l < Lq) {
            size_t base = ((size_t)b * Lq + l) * (3 * Cc) + h * Dd;
            float4 qv = *(const float4*)&qkv[base + d4];
            float4 kv = *(const float4*)&qkv[base + Cc + d4];
            float4 vv = *(const float4*)&qkv[base + 2 * Cc + d4];
            if (l >= NREG) {
                int dp = d4 ^ 32;
                float4 qp = *(const float4*)&qkv[base + dp];
                float4 kp = *(const float4*)&qkv[base + Cc + dp];
                float4 cs = *(const float4*)&rope[(size_t)(l - NREG) * Dd + d4];
                float4 sn = *(const float4*)&rope[(size_t)ROPE_PLANE +
                                                  (size_t)(l - NREG) * Dd + d4];
                float sgn = (d4 < 32) ? -1.f : 1.f;
                qv.x = qv.x * cs.x + sgn * qp.x * sn.x;
                qv.y = qv.y * cs.y + sgn * qp.y * sn.y;
                qv.z = qv.z * cs.z + sgn * qp.z * sn.z;
                qv.w = qv.w * cs.w + sgn * qp.w * sn.w;
                kv.x = kv.x * cs.x + sgn * kp.x * sn.x;
                kv.y = kv.y * cs.y + sgn * kp.y * sn.y;
                kv.z = kv.z * cs.z + sgn * kp.z * sn.z;
                kv.w = kv.w * cs.w + sgn * kp.w * sn.w;
            }
            size_t oidx = (bh * Lq + l) * Dd + d4;
            *(float4*)&Q[oidx] = qv;
            unsigned h0, l0w, h1, l1w;
            split2(kv.x, kv.y, h0, l0w);
            split2(kv.z, kv.w, h1, l1w);
            *(uint2*)&KHI[oidx] = make_uint2(h0, h1);
            *(uint2*)&KLO[oidx] = make_uint2(l0w, l1w);
            vh[d4 + 0][ll] = __float2half_rn(vv.x);
            vh[d4 + 1][ll] = __float2half_rn(vv.y);
            vh[d4 + 2][ll] = __float2half_rn(vv.z);
            vh[d4 + 3][ll] = __float2half_rn(vv.w);
        } else {
            __half z = __float2half_rn(0.f);
#pragma unroll
            for (int jj = 0; jj < 4; jj++) vh[d4 + jj][ll] = z;
        }
    }
    __syncthreads();
    for (int it = tid; it < 64 * 8; it += 256) {
        int d = it >> 3, c8 = (it & 7) * 8;
        int l = lt0 + c8;
        if (l < LPAD)
            *(uint4*)&VT[(bh * Dd + d) * LPAD + l] = *(uint4*)&vh[d][c8];
    }
}

// ---------------------------------------------------------------------------
// Flash attention: QK bf16x3, exp2 softmax, PV = P(fp16 single) x V(fp16).
// Q in smem, cp.async double-buffered KV, 2 CTAs/SM.
// ---------------------------------------------------------------------------
#define QARR (128 * 72)
#define FARR (64 * 72)
#define FBUF (3 * FARR)
#define FLASH_SMEM ((2 * QARR + 2 * FBUF) * 2)

__global__ __launch_bounds__(256, 2) void flash_mma_db(
    const float* __restrict__ Q, const __nv_bfloat16* __restrict__ KHI,
    const __nv_bfloat16* __restrict__ KLO, const __half* __restrict__ VT,
    float* __restrict__ O) {
    extern __shared__ __nv_bfloat16 fsm[];
    __nv_bfloat16* Qh = fsm;
    __nv_bfloat16* Ql = fsm + QARR;
    __nv_bfloat16* KV = fsm + 2 * QARR;

    int tid = threadIdx.x;
    int warp = tid >> 5, lane = tid & 31;
    int g = lane >> 2, t = lane & 3;
    int q0 = blockIdx.x * 128;
    int h = blockIdx.y, b = blockIdx.z;
    size_t bh = (size_t)(b * Hh + h);
    const float* Qb = Q + bh * Lq * Dd;
    const __nv_bfloat16* KHIb = KHI + bh * Lq * Dd;
    const __nv_bfloat16* KLOb = KLO + bh * Lq * Dd;
    const __half* VTb = VT + bh * Dd * LPAD;

    int r0 = q0 + warp * 16 + g;
    int r1 = r0 + 8;

    int mi = lane >> 3, rr = lane & 7;
    unsigned ldsm_off = (((mi >> 1) * 8 + rr) * 72 + (mi & 1) * 8) * 2;
    unsigned q_off = (((mi & 1) * 8 + rr) * 72 + (mi >> 1) * 8) * 2;

    const float scale = 0.125f * 1.4426950408889634f;
    for (int it = tid; it < 128 * 16; it += 256) {
        int row = it >> 4, c4 = (it & 15) * 4;
        int l = q0 + row;
        float4 v = make_float4(0.f, 0.f, 0.f, 0.f);
        if (l < Lq) v = *(const float4*)&Qb[(size_t)l * Dd + c4];
        unsigned h0, l0w, h1, l1w;
        split2(v.x * scale, v.y * scale, h0, l0w);
        split2(v.z * scale, v.w * scale, h1, l1w);
        *(uint2*)&Qh[row * 72 + c4] = make_uint2(h0, h1);
        *(uint2*)&Ql[row * 72 + c4] = make_uint2(l0w, l1w);
    }

    float m0 = -1e30f, m1 = -1e30f, l0 = 0.f, l1 = 0.f;
    float o[8][4];
#pragma unroll
    for (int nf = 0; nf < 8; nf++)
#pragma unroll
        for (int q = 0; q < 4; q++) o[nf][q] = 0.f;

    auto stage = [&](int buf, int kt) {
        int k0 = kt * 64;
        __nv_bfloat16* B = KV + buf * FBUF;
#pragma unroll
        for (int p = 0; p < 6; p++) {
            int it = tid + p * 256;
            int arr = it >> 9;
            int idx = it & 511;
            int row = idx >> 3, c8 = (idx & 7) * 8;
            __nv_bfloat16* dst = B + arr * FARR + row * 72 + c8;
            if (arr < 2) {
                int kr = k0 + row;
                int krc = kr < Lq ? kr : 0;
                const __nv_bfloat16* src =
                    (arr == 0 ? KHIb : KLOb) + (size_t)krc * Dd + c8;
                cpa16(smaddr(dst), src, kr < Lq ? 16 : 0);
            } else {
                int col = k0 + c8;
                int colc = col < LPAD ? col : 0;
                const __half* src = VTb + (size_t)row * LPAD + colc;
                cpa16(smaddr(dst), src, col < LPAD ? 16 : 0);
            }
        }
    };

    int nkt = (Lq + 63) / 64;  // 33
    stage(0, 0);
    CPA_COMMIT;

    unsigned qhB = smaddr(Qh) + warp * 16 * 72 * 2 + q_off;
    unsigned qlB = qhB + QARR * 2;

    for (int kt = 0; kt < nkt; kt++) {
        CPA_WAIT0;
        __syncthreads();
        if (kt + 1 < nkt) {
            stage((kt + 1) & 1, kt + 1);
            CPA_COMMIT;
        }
        int k0 = kt * 64;
        unsigned khiB = smaddr(KV + (kt & 1) * FBUF) + ldsm_off;
        unsigned kloB = khiB + FARR * 2;
        unsigned vB = khiB + 2 * FARR * 2;

        // S = Q K^T (bf16x3), log2-domain logits
        float s[8][4];
#pragma unroll
        for (int nf = 0; nf < 8; nf++)
#pragma unroll
            for (int q = 0; q < 4; q++) s[nf][q] = 0.f;

#pragma unroll
        for (int ks = 0; ks < 4; ks++) {
            unsigned qh4[4], ql4[4];
            ldsm_x4(qh4[0], qh4[1], qh4[2], qh4[3], qhB + ks * 32);
            ldsm_x4(ql4[0], ql4[1], ql4[2], ql4[3], qlB + ks * 32);
#pragma unroll
            for (int q = 0; q < 4; q++) {
                unsigned off = (q * 16 * 72 + ks * 16) * 2;
                unsigned bh0[2], bh1[2], bl0[2], bl1[2];
                ldsm_x4(bh0[0], bh0[1], bh1[0], bh1[1], khiB + off);
                ldsm_x4(bl0[0], bl0[1], bl1[0], bl1[1], kloB + off);
                mma_bf16(s[2 * q], qh4, bh0);
                mma_bf16(s[2 * q], qh4, bl0);
                mma_bf16(s[2 * q], ql4, bh0);
                mma_bf16(s[2 * q + 1], qh4, bh1);
                mma_bf16(s[2 * q + 1], qh4, bl1);
                mma_bf16(s[2 * q + 1], ql4, bh1);
            }
        }

        // mask + online softmax (exp2 domain)
#pragma unroll
        for (int nf = 0; nf < 8; nf++) {
            int c = k0 + nf * 8 + 2 * t;
            if (c >= Lq) s[nf][0] = s[nf][2] = -1e30f;
            if (c + 1 >= Lq) s[nf][1] = s[nf][3] = -1e30f;
        }
        float mx0 = -1e30f, mx1 = -1e30f;
#pragma unroll
        for (int nf = 0; nf < 8; nf++) {
            mx0 = fmaxf(mx0, fmaxf(s[nf][0], s[nf][1]));
            mx1 = fmaxf(mx1, fmaxf(s[nf][2], s[nf][3]));
        }
        mx0 = fmaxf(mx0, __shfl_xor_sync(0xffffffffu, mx0, 1));
        mx0 = fmaxf(mx0, __shfl_xor_sync(0xffffffffu, mx0, 2));
        mx1 = fmaxf(mx1, __shfl_xor_sync(0xffffffffu, mx1, 1));
        mx1 = fmaxf(mx1, __shfl_xor_sync(0xffffffffu, mx1, 2));
        float mn0 = fmaxf(m0, mx0), mn1 = fmaxf(m1, mx1);
        float a0 = ex2f(m0 - mn0), a1 = ex2f(m1 - mn1);
        m0 = mn0;
        m1 = mn1;
        float rs0 = 0.f, rs1 = 0.f;
#pragma unroll
        for (int nf = 0; nf < 8; nf++) {
            s[nf][0] = ex2f(s[nf][0] - mn0);
            s[nf][1] = ex2f(s[nf][1] - mn0);
            s[nf][2] = ex2f(s[nf][2] - mn1);
            s[nf][3] = ex2f(s[nf][3] - mn1);
            rs0 += s[nf][0] + s[nf][1];
            rs1 += s[nf][2] + s[nf][3];
        }
        rs0 += __shfl_xor_sync(0xffffffffu, rs0, 1);
        rs0 += __shfl_xor_sync(0xffffffffu, rs0, 2);
        rs1 += __shfl_xor_sync(0xffffffffu, rs1, 1);
        rs1 += __shfl_xor_sync(0xffffffffu, rs1, 2);
        l0 = l0 * a0 + rs0;
        l1 = l1 * a1 + rs1;
#pragma unroll
        for (int nf = 0; nf < 8; nf++) {
            o[nf][0] *= a0;
            o[nf][1] *= a0;
            o[nf][2] *= a1;
            o[nf][3] *= a1;
        }

        // O += P V : P single fp16 x V fp16 (32 mma)
#pragma unroll
        for (int ks = 0; ks < 4; ks++) {
            unsigned ph[4];
            ph[0] = pack_h2(s[2 * ks][0], s[2 * ks][1]);
            ph[1] = pack_h2(s[2 * ks][2], s[2 * ks][3]);
            ph[2] = pack_h2(s[2 * ks + 1][0], s[2 * ks + 1][1]);
            ph[3] = pack_h2(s[2 * ks + 1][2], s[2 * ks + 1][3]);
#pragma unroll
            for (int q = 0; q < 4; q++) {
                unsigned off = (q * 16 * 72 + ks * 16) * 2;
                unsigned vh0[2], vh1[2];
                ldsm_x4(vh0[0], vh0[1], vh1[0], vh1[1], vB + off);
                mma_f16(o[2 * q], ph, vh0);
                mma_f16(o[2 * q + 1], ph, vh1);
            }
        }
    }

    float inv0 = 1.f / l0, inv1 = 1.f / l1;
#pragma unroll
    for (int nf = 0; nf < 8; nf++) {
        int col = h * Dd + nf * 8 + 2 * t;
        if (r0 < Lq)
            *(float2*)&O[((size_t)b * Lq + r0) * Cc + col] =
                make_float2(o[nf][0] * inv0, o[nf][1] * inv0);
        if (r1 < Lq)
            *(float2*)&O[((size_t)b * Lq + r1) * Cc + col] =
                make_float2(o[nf][2] * inv1, o[nf][3] * inv1);
    }
}

// ---------------------------------------------------------------------------
// LayerNorm; output rounded to tf32 (round-11 version, unchanged)
// ---------------------------------------------------------------------------
__global__ void ln_kernel(const float* __restrict__ in,
                          const float* __restrict__ gamma,
                          const float* __restrict__ beta,
                          float* __restrict__ out) {
    int row = blockIdx.x;
    int tid = threadIdx.x;
    const float* r = in + (size_t)row * Cc;
    float4 v = *(const float4*)&r[tid * 4];
    float s = v.x + v.y + v.z + v.w;
    float s2 = v.x * v.x + v.y * v.y + v.z * v.z + v.w * v.w;
#pragma unroll
    for (int off = 16; off >= 1; off >>= 1) {
        s += __shfl_xor_sync(0xffffffffu, s, off);
        s2 += __shfl_xor_sync(0xffffffffu, s2, off);
    }
    __shared__ float ws[8], ws2[8];
    __shared__ float mean_s, rstd_s;
    int wid = tid >> 5, lane = tid & 31;
    if (lane == 0) {
        ws[wid] = s;
        ws2[wid] = s2;
    }
    __syncthreads();
    if (tid == 0) {
        float S = 0.f, S2 = 0.f;
#pragma unroll
        for (int i = 0; i < 8; i++) {
            S += ws[i];
            S2 += ws2[i];
        }
        float mean = S * (1.f / Cc);
        float var = S2 * (1.f / Cc) - mean * mean;
        mean_s = mean;
        rstd_s = rsqrtf(var + 1e-5f);
    }
    __syncthreads();
    float mean = mean_s, rstd = rstd_s;
    float4 g = *(const float4*)&gamma[tid * 4];
    float4 bt = *(const float4*)&beta[tid * 4];
    float4 o;
    o.x = __uint_as_float(f2tf32((v.x - mean) * rstd * g.x + bt.x));
    o.y = __uint_as_float(f2tf32((v.y - mean) * rstd * g.y + bt.y));
    o.z = __uint_as_float(f2tf32((v.z - mean) * rstd * g.z + bt.z));
    o.w = __uint_as_float(f2tf32((v.w - mean) * rstd * g.w + bt.w));
    *(float4*)&out[(size_t)row * Cc + tid * 4] = o;
}

// ---------------------------------------------------------------------------
extern "C" void kernel_launch(void* const* d_in, const int* in_sizes, int n_in,
                              void* d_out, int out_size) {
    const float* x = (const float*)d_in[0];
    const float* rope = (const float*)d_in[1];
    const float* Wqkv = (const float*)d_in[2];
    const float* bqkv = (const float*)d_in[3];
    const float* Wproj = (const float*)d_in[4];
    const float* bproj = (const float*)d_in[5];
    const float* gamma = (const float*)d_in[6];
    const float* beta = (const float*)d_in[7];
    float* out = (float*)d_out;

    float *qkv, *q, *attn, *ln, *xr, *wqkvT, *wprojT;
    __nv_bfloat16 *khi, *klo;
    __half* vt;
    cudaGetSymbolAddress((void**)&qkv, g_qkv);
    cudaGetSymbolAddress((void**)&q, g_q);
    cudaGetSymbolAddress((void**)&khi, g_khi);
    cudaGetSymbolAddress((void**)&klo, g_klo);
    cudaGetSymbolAddress((void**)&vt, g_vt);
    cudaGetSymbolAddress((void**)&attn, g_attn);
    cudaGetSymbolAddress((void**)&ln, g_ln);
    cudaGetSymbolAddress((void**)&xr, g_xr);
    cudaGetSymbolAddress((void**)&wqkvT, g_wqkvT);
    cudaGetSymbolAddress((void**)&wprojT, g_wprojT);

    const int M = ROWS;  // 8208

    // 0) pre-round x; transpose+round weights to [N][K]
    int nx4 = ROWS * Cc / 4;
    round_tf32_kernel<<<(nx4 + 255) / 256, 256>>>(x, xr, nx4);
    transpose_round_kernel<<<dim3(3 * Cc / 32, Cc / 32), dim3(32, 8)>>>(
        Wqkv, wqkvT, Cc, 3 * Cc);
    transpose_round_kernel<<<dim3(Cc / 32, Cc / 32), dim3(32, 8)>>>(
        Wproj, wprojT, Cc, Cc);

    // 1) QKV GEMM (tf32, 128x256 tiles)
    cudaFuncSetAttribute(gemm_tf32_db, cudaFuncAttributeMaxDynamicSharedMemorySize,
                         GEMM_SMEM);
    gemm_tf32_db<<<dim3(3 * Cc / 256, (M + 127) / 128), 256, GEMM_SMEM>>>(
        xr, wqkvT, bqkv, qkv, M, 3 * Cc, Cc);

    // 2) RoPE + split + transpose
    rope_split_kernel<<<dim3((Lq + 63) / 64, Hh, Bb), 256>>>(
        qkv, rope, q, khi, klo, vt);

    // 3) Flash attention (P single-fp16 PV)
    cudaFuncSetAttribute(flash_mma_db, cudaFuncAttributeMaxDynamicSharedMemorySize,
                         FLASH_SMEM);
    flash_mma_db<<<dim3((Lq + 127) / 128, Hh, Bb), 256, FLASH_SMEM>>>(
        q, khi, klo, vt, attn);

    // 4) LayerNorm (emits tf32-rounded)
    ln_kernel<<<M, 256>>>(attn, gamma, beta, ln);

    // 5) Projection GEMM (tf32)
    gemm_tf32_db<<<dim3(Cc / 256, (M + 127) / 128), 256, GEMM_SMEM>>>(
        ln, wprojT, bproj, out, M, Cc, Cc);
}

// round 17
// speedup vs baseline: 1.5266x; 1.5266x over previous
#include <cuda_runtime.h>
#include <cuda_bf16.h>
#include <cuda_fp16.h>
#include <cstdint>

// Problem constants
#define Bb 4
#define Lq 2052
#define Cc 1024
#define Hh 16
#define Dd 64
#define NREG 4
#define ROWS (Bb * Lq)                  // 8208
#define ROPE_PLANE ((Lq - NREG) * Dd)   // 2048*64
#define LPAD 2064                       // padded L for transposed V rows

// -------- scratch (device globals; no allocation allowed) ------------------
__device__ float g_qkv[(size_t)ROWS * 3 * Cc];       // QKV GEMM output
__device__ float g_q[(size_t)Bb * Hh * Lq * Dd];     // Q fp32 [B,H,L,D]
__device__ __nv_bfloat16 g_khi[(size_t)Bb * Hh * Lq * Dd];
__device__ __nv_bfloat16 g_klo[(size_t)Bb * Hh * Lq * Dd];
__device__ __half g_vt[(size_t)Bb * Hh * Dd * LPAD];  // V^T fp16 [B,H,D,Lpad]
__device__ float g_attn[(size_t)ROWS * Cc];          // attention out [B,L,C]
__device__ float g_ln[(size_t)ROWS * Cc];            // LN out (tf32-rounded)
__device__ float g_xr[(size_t)ROWS * Cc];            // x rounded to tf32
__device__ float g_wqkvT[(size_t)3 * Cc * Cc];       // Wqkv^T [3C][C] tf32
__device__ float g_wprojT[(size_t)Cc * Cc];          // Wproj^T [C][C] tf32

// ---------------------------------------------------------------------------
// helpers
// ---------------------------------------------------------------------------
__device__ __forceinline__ unsigned f2tf32(float f) {
    unsigned u;
    asm("cvt.rna.tf32.f32 %0, %1;" : "=r"(u) : "f"(f));
    return u;
}

__device__ __forceinline__ float ex2f(float x) {
    float r;
    asm("ex2.approx.ftz.f32 %0, %1;" : "=f"(r) : "f"(x));
    return r;
}

__device__ __forceinline__ void mma_tf32(float* c, const unsigned* a,
                                         const unsigned* b) {
    asm volatile(
        "mma.sync.aligned.m16n8k8.row.col.f32.tf32.tf32.f32 "
        "{%0,%1,%2,%3}, {%4,%5,%6,%7}, {%8,%9}, {%0,%1,%2,%3};"
        : "+f"(c[0]), "+f"(c[1]), "+f"(c[2]), "+f"(c[3])
        : "r"(a[0]), "r"(a[1]), "r"(a[2]), "r"(a[3]), "r"(b[0]), "r"(b[1]));
}

__device__ __forceinline__ void mma_bf16(float* c, const unsigned* a,
                                         const unsigned* b) {
    asm volatile(
        "mma.sync.aligned.m16n8k16.row.col.f32.bf16.bf16.f32 "
        "{%0,%1,%2,%3}, {%4,%5,%6,%7}, {%8,%9}, {%0,%1,%2,%3};"
        : "+f"(c[0]), "+f"(c[1]), "+f"(c[2]), "+f"(c[3])
        : "r"(a[0]), "r"(a[1]), "r"(a[2]), "r"(a[3]), "r"(b[0]), "r"(b[1]));
}

__device__ __forceinline__ void mma_f16(float* c, const unsigned* a,
                                        const unsigned* b) {
    asm volatile(
        "mma.sync.aligned.m16n8k16.row.col.f32.f16.f16.f32 "
        "{%0,%1,%2,%3}, {%4,%5,%6,%7}, {%8,%9}, {%0,%1,%2,%3};"
        : "+f"(c[0]), "+f"(c[1]), "+f"(c[2]), "+f"(c[3])
        : "r"(a[0]), "r"(a[1]), "r"(a[2]), "r"(a[3]), "r"(b[0]), "r"(b[1]));
}

__device__ __forceinline__ void ldsm_x4(unsigned& r0, unsigned& r1,
                                        unsigned& r2, unsigned& r3,
                                        unsigned addr) {
    asm volatile(
        "ldmatrix.sync.aligned.m8n8.x4.shared.b16 {%0,%1,%2,%3}, [%4];"
        : "=r"(r0), "=r"(r1), "=r"(r2), "=r"(r3)
        : "r"(addr));
}

__device__ __forceinline__ unsigned pack_bf16(float x, float y) {
    __nv_bfloat162 t = __floats2bfloat162_rn(x, y);
    return *(unsigned*)&t;
}

__device__ __forceinline__ void split2(float x, float y, unsigned& hi,
                                       unsigned& lo) {
    __nv_bfloat16 hx = __float2bfloat16_rn(x);
    __nv_bfloat16 hy = __float2bfloat16_rn(y);
    float rx = x - __bfloat162float(hx);
    float ry = y - __bfloat162float(hy);
    __nv_bfloat162 h;
    h.x = hx;
    h.y = hy;
    hi = *(unsigned*)&h;
    lo = pack_bf16(rx, ry);
}

__device__ __forceinline__ unsigned pack_h2(float x, float y) {
    __half2 t = __floats2half2_rn(x, y);
    return *(unsigned*)&t;
}

__device__ __forceinline__ unsigned smaddr(const void* p) {
    return (unsigned)__cvta_generic_to_shared(p);
}
__device__ __forceinline__ void cpa16(unsigned dst, const void* src, int sz) {
    asm volatile("cp.async.cg.shared.global [%0], [%1], 16, %2;" ::"r"(dst),
                 "l"(src), "r"(sz));
}
#define CPA_COMMIT asm volatile("cp.async.commit_group;")
#define CPA_WAIT0 asm volatile("cp.async.wait_group 0;" ::: "memory")

// ---------------------------------------------------------------------------
// prep: round x to tf32; transpose+round W -> WT [N][K]
// ---------------------------------------------------------------------------
__global__ void round_tf32_kernel(const float* __restrict__ src,
                                  float* __restrict__ dst, int n4) {
    int i = blockIdx.x * blockDim.x + threadIdx.x;
    if (i >= n4) return;
    float4 v = ((const float4*)src)[i];
    v.x = __uint_as_float(f2tf32(v.x));
    v.y = __uint_as_float(f2tf32(v.y));
    v.z = __uint_as_float(f2tf32(v.z));
    v.w = __uint_as_float(f2tf32(v.w));
    ((float4*)dst)[i] = v;
}

__global__ void transpose_round_kernel(const float* __restrict__ W,
                                       float* __restrict__ WT, int K, int N) {
    __shared__ float tile[32][33];
    int k0 = blockIdx.y * 32, n0 = blockIdx.x * 32;
    int tx = threadIdx.x, ty = threadIdx.y;
#pragma unroll
    for (int j = 0; j < 4; j++)
        tile[ty + j * 8][tx] = W[(size_t)(k0 + ty + j * 8) * N + n0 + tx];
    __syncthreads();
#pragma unroll
    for (int j = 0; j < 4; j++)
        WT[(size_t)(n0 + ty + j * 8) * K + k0 + tx] =
            __uint_as_float(f2tf32(tile[tx][ty + j * 8]));
}

// ---------------------------------------------------------------------------
// tf32 GEMM: block 128x256, BK=64, warp 64x64, double-buffered cp.async,
// both operands k-major + ldmatrix.  (round-11 passing version, unchanged)
// ---------------------------------------------------------------------------
#define GEMM_SMEM ((2 * 128 * 68 + 2 * 256 * 68) * 4)

__global__ __launch_bounds__(256) void gemm_tf32_db(
    const float* __restrict__ A, const float* __restrict__ BT,
    const float* __restrict__ bias, float* __restrict__ Cm,
    int M, int N, int K) {
    extern __shared__ float gsm[];
    float(*As)[128][68] = (float(*)[128][68])gsm;
    float(*Bs)[256][68] = (float(*)[256][68])(gsm + 2 * 128 * 68);

    int tid = threadIdx.x;
    int warp = tid >> 5, lane = tid & 31;
    int g = lane >> 2, t = lane & 3;
    int wm = (warp >> 2) * 64, wn = (warp & 3) * 64;
    int m0 = blockIdx.y * 128, n0 = blockIdx.x * 256;

    int j = lane >> 3, r = lane & 7;
    int aoff = ((j & 1) * 8 + r) * 68 + (j >> 1) * 4;
    int boff = ((j >> 1) * 8 + r) * 68 + (j & 1) * 4;

    float acc[4][8][4];
#pragma unroll
    for (int mt = 0; mt < 4; mt++)
#pragma unroll
        for (int nt = 0; nt < 8; nt++)
#pragma unroll
            for (int q = 0; q < 4; q++) acc[mt][nt][q] = 0.f;

    auto stage = [&](int buf, int k0) {
#pragma unroll
        for (int p = 0; p < 8; p++) {
            int it = tid + p * 256;
            int row = it >> 4, c4 = (it & 15) * 4;
            int ar = m0 + row;
            int arc = ar < M ? ar : 0;
            cpa16(smaddr(&As[buf][row][c4]),
                  &A[(size_t)arc * K + k0 + c4], ar < M ? 16 : 0);
        }
#pragma unroll
        for (int p = 0; p < 16; p++) {
            int it = tid + p * 256;
            int row = it >> 4, c4 = (it & 15) * 4;
            cpa16(smaddr(&Bs[buf][row][c4]),
                  &BT[(size_t)(n0 + row) * K + k0 + c4], 16);
        }
    };

    int nk = K / 64;  // 16
    stage(0, 0);
    CPA_COMMIT;

    for (int kt = 0; kt < nk; kt++) {
        CPA_WAIT0;
        __syncthreads();
        if (kt + 1 < nk) {
            stage((kt + 1) & 1, (kt + 1) * 64);
            CPA_COMMIT;
        }
        int buf = kt & 1;
        unsigned Abase = smaddr(&As[buf][0][0]);
        unsigned Bbase = smaddr(&Bs[buf][0][0]);
#pragma unroll
        for (int ks = 0; ks < 8; ks++) {
            unsigned af[4][4], bf[8][2];
#pragma unroll
            for (int mt = 0; mt < 4; mt++) {
                unsigned ad =
                    Abase + ((wm + mt * 16) * 68 + ks * 8 + aoff) * 4;
                ldsm_x4(af[mt][0], af[mt][1], af[mt][2], af[mt][3], ad);
            }
#pragma unroll
            for (int pr = 0; pr < 4; pr++) {
                unsigned bd =
                    Bbase + ((wn + pr * 16) * 68 + ks * 8 + boff) * 4;
                ldsm_x4(bf[2 * pr][0], bf[2 * pr][1], bf[2 * pr + 1][0],
                        bf[2 * pr + 1][1], bd);
            }
#pragma unroll
            for (int mt = 0; mt < 4; mt++)
#pragma unroll
                for (int nt = 0; nt < 8; nt++)
                    mma_tf32(acc[mt][nt], af[mt], bf[nt]);
        }
    }

#pragma unroll
    for (int mt = 0; mt < 4; mt++) {
        int row = m0 + wm + mt * 16 + g;
#pragma unroll
        for (int nt = 0; nt < 8; nt++) {
            int col = n0 + wn + nt * 8 + t * 2;
            float b0 = bias[col], b1 = bias[col + 1];
            if (row < M) {
                *(float2*)&Cm[(size_t)row * N + col] =
                    make_float2(acc[mt][nt][0] + b0, acc[mt][nt][1] + b1);
            }
            if (row + 8 < M) {
                *(float2*)&Cm[(size_t)(row + 8) * N + col] =
                    make_float2(acc[mt][nt][2] + b0, acc[mt][nt][3] + b1);
            }
        }
    }
}

// ---------------------------------------------------------------------------
// RoPE + split + transpose: Q fp32; K hi/lo bf16 [B,H,L,D]; V^T fp16 [B,H,D,LPAD]
// ---------------------------------------------------------------------------
__global__ __launch_bounds__(256) void rope_split_kernel(
    const float* __restrict__ qkv, const float* __restrict__ rope,
    float* __restrict__ Q, __nv_bfloat16* __restrict__ KHI,
    __nv_bfloat16* __restrict__ KLO, __half* __restrict__ VT) {
    __shared__ __half vh[64][72];  // [d][l_local]
    int lt0 = blockIdx.x * 64, h = blockIdx.y, b = blockIdx.z;
    int tid = threadIdx.x;
    size_t bh = (size_t)(b * Hh + h);

    for (int it = tid; it < 64 * 16; it += 256) {
        int ll = it >> 4, d4 = (it & 15) * 4;
        int l = lt0 + ll;
        if (l < Lq) {
            size_t base = ((size_t)b * Lq + l) * (3 * Cc) + h * Dd;
            float4 qv = *(const float4*)&qkv[base + d4];
            float4 kv = *(const float4*)&qkv[base + Cc + d4];
            float4 vv = *(const float4*)&qkv[base + 2 * Cc + d4];
            if (l >= NREG) {
                int dp = d4 ^ 32;
                float4 qp = *(const float4*)&qkv[base + dp];
                float4 kp = *(const float4*)&qkv[base + Cc + dp];
                float4 cs = *(const float4*)&rope[(size_t)(l - NREG) * Dd + d4];
                float4 sn = *(const float4*)&rope[(size_t)ROPE_PLANE +
                                                  (size_t)(l - NREG) * Dd + d4];
                float sgn = (d4 < 32) ? -1.f : 1.f;
                qv.x = qv.x * cs.x + sgn * qp.x * sn.x;
                qv.y = qv.y * cs.y + sgn * qp.y * sn.y;
                qv.z = qv.z * cs.z + sgn * qp.z * sn.z;
                qv.w = qv.w * cs.w + sgn * qp.w * sn.w;
                kv.x = kv.x * cs.x + sgn * kp.x * sn.x;
                kv.y = kv.y * cs.y + sgn * kp.y * sn.y;
                kv.z = kv.z * cs.z + sgn * kp.z * sn.z;
                kv.w = kv.w * cs.w + sgn * kp.w * sn.w;
            }
            size_t oidx = (bh * Lq + l) * Dd + d4;
            *(float4*)&Q[oidx] = qv;
            unsigned h0, l0w, h1, l1w;
            split2(kv.x, kv.y, h0, l0w);
            split2(kv.z, kv.w, h1, l1w);
            *(uint2*)&KHI[oidx] = make_uint2(h0, h1);
            *(uint2*)&KLO[oidx] = make_uint2(l0w, l1w);
            vh[d4 + 0][ll] = __float2half_rn(vv.x);
            vh[d4 + 1][ll] = __float2half_rn(vv.y);
            vh[d4 + 2][ll] = __float2half_rn(vv.z);
            vh[d4 + 3][ll] = __float2half_rn(vv.w);
        } else {
            __half z = __float2half_rn(0.f);
#pragma unroll
            for (int jj = 0; jj < 4; jj++) vh[d4 + jj][ll] = z;
        }
    }
    __syncthreads();
    for (int it = tid; it < 64 * 8; it += 256) {
        int d = it >> 3, c8 = (it & 7) * 8;
        int l = lt0 + c8;
        if (l < LPAD)
            *(uint4*)&VT[(bh * Dd + d) * LPAD + l] = *(uint4*)&vh[d][c8];
    }
}

// ---------------------------------------------------------------------------
// Flash attention: QK bf16x3, exp2 softmax, PV = P(fp16 single) x V(fp16).
// Q in smem, cp.async double-buffered KV, 2 CTAs/SM.
// ---------------------------------------------------------------------------
#define QARR (128 * 72)
#define FARR (64 * 72)
#define FBUF (3 * FARR)
#define FLASH_SMEM ((2 * QARR + 2 * FBUF) * 2)

__global__ __launch_bounds__(256, 2) void flash_mma_db(
    const float* __restrict__ Q, const __nv_bfloat16* __restrict__ KHI,
    const __nv_bfloat16* __restrict__ KLO, const __half* __restrict__ VT,
    float* __restrict__ O) {
    extern __shared__ __nv_bfloat16 fsm[];
    __nv_bfloat16* Qh = fsm;
    __nv_bfloat16* Ql = fsm + QARR;
    __nv_bfloat16* KV = fsm + 2 * QARR;

    int tid = threadIdx.x;
    int warp = tid >> 5, lane = tid & 31;
    int g = lane >> 2, t = lane & 3;
    int q0 = blockIdx.x * 128;
    int h = blockIdx.y, b = blockIdx.z;
    size_t bh = (size_t)(b * Hh + h);
    const float* Qb = Q + bh * Lq * Dd;
    const __nv_bfloat16* KHIb = KHI + bh * Lq * Dd;
    const __nv_bfloat16* KLOb = KLO + bh * Lq * Dd;
    const __half* VTb = VT + bh * Dd * LPAD;

    int r0 = q0 + warp * 16 + g;
    int r1 = r0 + 8;

    int mi = lane >> 3, rr = lane & 7;
    unsigned ldsm_off = (((mi >> 1) * 8 + rr) * 72 + (mi & 1) * 8) * 2;
    unsigned q_off = (((mi & 1) * 8 + rr) * 72 + (mi >> 1) * 8) * 2;

    const float scale = 0.125f * 1.4426950408889634f;
    for (int it = tid; it < 128 * 16; it += 256) {
        int row = it >> 4, c4 = (it & 15) * 4;
        int l = q0 + row;
        float4 v = make_float4(0.f, 0.f, 0.f, 0.f);
        if (l < Lq) v = *(const float4*)&Qb[(size_t)l * Dd + c4];
        unsigned h0, l0w, h1, l1w;
        split2(v.x * scale, v.y * scale, h0, l0w);
        split2(v.z * scale, v.w * scale, h1, l1w);
        *(uint2*)&Qh[row * 72 + c4] = make_uint2(h0, h1);
        *(uint2*)&Ql[row * 72 + c4] = make_uint2(l0w, l1w);
    }

    float m0 = -1e30f, m1 = -1e30f, l0 = 0.f, l1 = 0.f;
    float o[8][4];
#pragma unroll
    for (int nf = 0; nf < 8; nf++)
#pragma unroll
        for (int q = 0; q < 4; q++) o[nf][q] = 0.f;

    auto stage = [&](int buf, int kt) {
        int k0 = kt * 64;
        __nv_bfloat16* B = KV + buf * FBUF;
#pragma unroll
        for (int p = 0; p < 6; p++) {
            int it = tid + p * 256;
            int arr = it >> 9;
            int idx = it & 511;
            int row = idx >> 3, c8 = (idx & 7) * 8;
            __nv_bfloat16* dst = B + arr * FARR + row * 72 + c8;
            if (arr < 2) {
                int kr = k0 + row;
                int krc = kr < Lq ? kr : 0;
                const __nv_bfloat16* src =
                    (arr == 0 ? KHIb : KLOb) + (size_t)krc * Dd + c8;
                cpa16(smaddr(dst), src, kr < Lq ? 16 : 0);
            } else {
                int col = k0 + c8;
                int colc = col < LPAD ? col : 0;
                const __half* src = VTb + (size_t)row * LPAD + colc;
                cpa16(smaddr(dst), src, col < LPAD ? 16 : 0);
            }
        }
    };

    int nkt = (Lq + 63) / 64;  // 33
    stage(0, 0);
    CPA_COMMIT;

    unsigned qhB = smaddr(Qh) + warp * 16 * 72 * 2 + q_off;
    unsigned qlB = qhB + QARR * 2;

    for (int kt = 0; kt < nkt; kt++) {
        CPA_WAIT0;
        __syncthreads();
        if (kt + 1 < nkt) {
            stage((kt + 1) & 1, kt + 1);
            CPA_COMMIT;
        }
        int k0 = kt * 64;
        unsigned khiB = smaddr(KV + (kt & 1) * FBUF) + ldsm_off;
        unsigned kloB = khiB + FARR * 2;
        unsigned vB = khiB + 2 * FARR * 2;

        // S = Q K^T (bf16x3), log2-domain logits
        float s[8][4];
#pragma unroll
        for (int nf = 0; nf < 8; nf++)
#pragma unroll
            for (int q = 0; q < 4; q++) s[nf][q] = 0.f;

#pragma unroll
        for (int ks = 0; ks < 4; ks++) {
            unsigned qh4[4], ql4[4];
            ldsm_x4(qh4[0], qh4[1], qh4[2], qh4[3], qhB + ks * 32);
            ldsm_x4(ql4[0], ql4[1], ql4[2], ql4[3], qlB + ks * 32);
#pragma unroll
            for (int q = 0; q < 4; q++) {
                unsigned off = (q * 16 * 72 + ks * 16) * 2;
                unsigned bh0[2], bh1[2], bl0[2], bl1[2];
                ldsm_x4(bh0[0], bh0[1], bh1[0], bh1[1], khiB + off);
                ldsm_x4(bl0[0], bl0[1], bl1[0], bl1[1], kloB + off);
                mma_bf16(s[2 * q], qh4, bh0);
                mma_bf16(s[2 * q], qh4, bl0);
                mma_bf16(s[2 * q], ql4, bh0);
                mma_bf16(s[2 * q + 1], qh4, bh1);
                mma_bf16(s[2 * q + 1], qh4, bl1);
                mma_bf16(s[2 * q + 1], ql4, bh1);
            }
        }

        // mask + online softmax (exp2 domain)
#pragma unroll
        for (int nf = 0; nf < 8; nf++) {
            int c = k0 + nf * 8 + 2 * t;
            if (c >= Lq) s[nf][0] = s[nf][2] = -1e30f;
            if (c + 1 >= Lq) s[nf][1] = s[nf][3] = -1e30f;
        }
        float mx0 = -1e30f, mx1 = -1e30f;
#pragma unroll
        for (int nf = 0; nf < 8; nf++) {
            mx0 = fmaxf(mx0, fmaxf(s[nf][0], s[nf][1]));
            mx1 = fmaxf(mx1, fmaxf(s[nf][2], s[nf][3]));
        }
        mx0 = fmaxf(mx0, __shfl_xor_sync(0xffffffffu, mx0, 1));
        mx0 = fmaxf(mx0, __shfl_xor_sync(0xffffffffu, mx0, 2));
        mx1 = fmaxf(mx1, __shfl_xor_sync(0xffffffffu, mx1, 1));
        mx1 = fmaxf(mx1, __shfl_xor_sync(0xffffffffu, mx1, 2));
        float mn0 = fmaxf(m0, mx0), mn1 = fmaxf(m1, mx1);
        float a0 = ex2f(m0 - mn0), a1 = ex2f(m1 - mn1);
        m0 = mn0;
        m1 = mn1;
        float rs0 = 0.f, rs1 = 0.f;
#pragma unroll
        for (int nf = 0; nf < 8; nf++) {
            s[nf][0] = ex2f(s[nf][0] - mn0);
            s[nf][1] = ex2f(s[nf][1] - mn0);
            s[nf][2] = ex2f(s[nf][2] - mn1);
            s[nf][3] = ex2f(s[nf][3] - mn1);
            rs0 += s[nf][0] + s[nf][1];
            rs1 += s[nf][2] + s[nf][3];
        }
        rs0 += __shfl_xor_sync(0xffffffffu, rs0, 1);
        rs0 += __shfl_xor_sync(0xffffffffu, rs0, 2);
        rs1 += __shfl_xor_sync(0xffffffffu, rs1, 1);
        rs1 += __shfl_xor_sync(0xffffffffu, rs1, 2);
        l0 = l0 * a0 + rs0;
        l1 = l1 * a1 + rs1;
#pragma unroll
        for (int nf = 0; nf < 8; nf++) {
            o[nf][0] *= a0;
            o[nf][1] *= a0;
            o[nf][2] *= a1;
            o[nf][3] *= a1;
        }

        // O += P V : P single fp16 x V fp16 (32 mma)
#pragma unroll
        for (int ks = 0; ks < 4; ks++) {
            unsigned ph[4];
            ph[0] = pack_h2(s[2 * ks][0], s[2 * ks][1]);
            ph[1] = pack_h2(s[2 * ks][2], s[2 * ks][3]);
            ph[2] = pack_h2(s[2 * ks + 1][0], s[2 * ks + 1][1]);
            ph[3] = pack_h2(s[2 * ks + 1][2], s[2 * ks + 1][3]);
#pragma unroll
            for (int q = 0; q < 4; q++) {
                unsigned off = (q * 16 * 72 + ks * 16) * 2;
                unsigned vh0[2], vh1[2];
                ldsm_x4(vh0[0], vh0[1], vh1[0], vh1[1], vB + off);
                mma_f16(o[2 * q], ph, vh0);
                mma_f16(o[2 * q + 1], ph, vh1);
            }
        }
    }

    float inv0 = 1.f / l0, inv1 = 1.f / l1;
#pragma unroll
    for (int nf = 0; nf < 8; nf++) {
        int col = h * Dd + nf * 8 + 2 * t;
        if (r0 < Lq)
            *(float2*)&O[((size_t)b * Lq + r0) * Cc + col] =
                make_float2(o[nf][0] * inv0, o[nf][1] * inv0);
        if (r1 < Lq)
            *(float2*)&O[((size_t)b * Lq + r1) * Cc + col] =
                make_float2(o[nf][2] * inv1, o[nf][3] * inv1);
    }
}

// ---------------------------------------------------------------------------
// LayerNorm; output rounded to tf32 (round-11 version, unchanged)
// ---------------------------------------------------------------------------
__global__ void ln_kernel(const float* __restrict__ in,
                          const float* __restrict__ gamma,
                          const float* __restrict__ beta,
                          float* __restrict__ out) {
    int row = blockIdx.x;
    int tid = threadIdx.x;
    const float* r = in + (size_t)row * Cc;
    float4 v = *(const float4*)&r[tid * 4];
    float s = v.x + v.y + v.z + v.w;
    float s2 = v.x * v.x + v.y * v.y + v.z * v.z + v.w * v.w;
#pragma unroll
    for (int off = 16; off >= 1; off >>= 1) {
        s += __shfl_xor_sync(0xffffffffu, s, off);
        s2 += __shfl_xor_sync(0xffffffffu, s2, off);
    }
    __shared__ float ws[8], ws2[8];
    __shared__ float mean_s, rstd_s;
    int wid = tid >> 5, lane = tid & 31;
    if (lane == 0) {
        ws[wid] = s;
        ws2[wid] = s2;
    }
    __syncthreads();
    if (tid == 0) {
        float S = 0.f, S2 = 0.f;
#pragma unroll
        for (int i = 0; i < 8; i++) {
            S += ws[i];
            S2 += ws2[i];
        }
        float mean = S * (1.f / Cc);
        float var = S2 * (1.f / Cc) - mean * mean;
        mean_s = mean;
        rstd_s = rsqrtf(var + 1e-5f);
    }
    __syncthreads();
    float mean = mean_s, rstd = rstd_s;
    float4 g = *(const float4*)&gamma[tid * 4];
    float4 bt = *(const float4*)&beta[tid * 4];
    float4 o;
    o.x = __uint_as_float(f2tf32((v.x - mean) * rstd * g.x + bt.x));
    o.y = __uint_as_float(f2tf32((v.y - mean) * rstd * g.y + bt.y));
    o.z = __uint_as_float(f2tf32((v.z - mean) * rstd * g.z + bt.z));
    o.w = __uint_as_float(f2tf32((v.w - mean) * rstd * g.w + bt.w));
    *(float4*)&out[(size_t)row * Cc + tid * 4] = o;
}

// ---------------------------------------------------------------------------
extern "C" void kernel_launch(void* const* d_in, const int* in_sizes, int n_in,
                              void* d_out, int out_size) {
    const float* x = (const float*)d_in[0];
    const float* rope = (const float*)d_in[1];
    const float* Wqkv = (const float*)d_in[2];
    const float* bqkv = (const float*)d_in[3];
    const float* Wproj = (const float*)d_in[4];
    const float* bproj = (const float*)d_in[5];
    const float* gamma = (const float*)d_in[6];
    const float* beta = (const float*)d_in[7];
    float* out = (float*)d_out;

    float *qkv, *q, *attn, *ln, *xr, *wqkvT, *wprojT;
    __nv_bfloat16 *khi, *klo;
    __half* vt;
    cudaGetSymbolAddress((void**)&qkv, g_qkv);
    cudaGetSymbolAddress((void**)&q, g_q);
    cudaGetSymbolAddress((void**)&khi, g_khi);
    cudaGetSymbolAddress((void**)&klo, g_klo);
    cudaGetSymbolAddress((void**)&vt, g_vt);
    cudaGetSymbolAddress((void**)&attn, g_attn);
    cudaGetSymbolAddress((void**)&ln, g_ln);
    cudaGetSymbolAddress((void**)&xr, g_xr);
    cudaGetSymbolAddress((void**)&wqkvT, g_wqkvT);
    cudaGetSymbolAddress((void**)&wprojT, g_wprojT);

    const int M = ROWS;  // 8208

    // 0) pre-round x; transpose+round weights to [N][K]
    int nx4 = ROWS * Cc / 4;
    round_tf32_kernel<<<(nx4 + 255) / 256, 256>>>(x, xr, nx4);
    transpose_round_kernel<<<dim3(3 * Cc / 32, Cc / 32), dim3(32, 8)>>>(
        Wqkv, wqkvT, Cc, 3 * Cc);
    transpose_round_kernel<<<dim3(Cc / 32, Cc / 32), dim3(32, 8)>>>(
        Wproj, wprojT, Cc, Cc);

    // 1) QKV GEMM (tf32, 128x256 tiles)
    cudaFuncSetAttribute(gemm_tf32_db, cudaFuncAttributeMaxDynamicSharedMemorySize,
                         GEMM_SMEM);
    gemm_tf32_db<<<dim3(3 * Cc / 256, (M + 127) / 128), 256, GEMM_SMEM>>>(
        xr, wqkvT, bqkv, qkv, M, 3 * Cc, Cc);

    // 2) RoPE + split + transpose
    rope_split_kernel<<<dim3((Lq + 63) / 64, Hh, Bb), 256>>>(
        qkv, rope, q, khi, klo, vt);

    // 3) Flash attention (P single-fp16 PV)
    cudaFuncSetAttribute(flash_mma_db, cudaFuncAttributeMaxDynamicSharedMemorySize,
                         FLASH_SMEM);
    flash_mma_db<<<dim3((Lq + 127) / 128, Hh, Bb), 256, FLASH_SMEM>>>(
        q, khi, klo, vt, attn);

    // 4) LayerNorm (emits tf32-rounded)
    ln_kernel<<<M, 256>>>(attn, gamma, beta, ln);

    // 5) Projection GEMM (tf32)
    gemm_tf32_db<<<dim3(Cc / 256, (M + 127) / 128), 256, GEMM_SMEM>>>(
        ln, wprojT, bproj, out, M, Cc, Cc);
}